// round 7
// baseline (speedup 1.0000x reference)
#include <cuda_runtime.h>
#include <cuda_fp16.h>
#include <cstdint>

#define D_DIM 768
#define V_OFF (10240*768)
#define TBM 128
#define TBN 128
#define NSTG 12                  // K stages of 64
#define ASTG 16384               // 128 rows * 128B
#define BSTG 16384
#define SMEM_TOTAL (3*ASTG + 3*BSTG)   // 98304

__device__ __half g_Bh[D_DIM*D_DIM];     // rn_f16(W), row-major (d, f)
__device__ __half g_Ah[16384*D_DIM];     // rn_f16(2*patch-1), (m, f)

__device__ __forceinline__ uint32_t smem_u32(const void* p){
  uint32_t a;
  asm("{ .reg .u64 t; cvta.to.shared.u64 t, %1; cvt.u32.u64 %0, t; }" : "=r"(a) : "l"(p));
  return a;
}
__device__ __forceinline__ void mma16(float* c, const uint32_t* a, uint32_t b0, uint32_t b1){
  asm volatile(
    "mma.sync.aligned.m16n8k16.row.col.f32.f16.f16.f32 "
    "{%0,%1,%2,%3},{%4,%5,%6,%7},{%8,%9},{%0,%1,%2,%3};\n"
    : "+f"(c[0]), "+f"(c[1]), "+f"(c[2]), "+f"(c[3])
    : "r"(a[0]), "r"(a[1]), "r"(a[2]), "r"(a[3]), "r"(b0), "r"(b1));
}
__device__ __forceinline__ void ldsm4(uint32_t* r, uint32_t addr){
  asm volatile("ldmatrix.sync.aligned.m8n8.x4.shared.b16 {%0,%1,%2,%3}, [%4];"
    : "=r"(r[0]), "=r"(r[1]), "=r"(r[2]), "=r"(r[3]) : "r"(addr));
}
__device__ __forceinline__ void cpasync16(uint32_t dst, const void* src){
  asm volatile("cp.async.cg.shared.global [%0], [%1], 16;"
               :: "r"(dst), "l"(src) : "memory");
}
__device__ __forceinline__ uint32_t pack2(float x, float y){
  __half2 h = __floats2half2_rn(x, y);
  return *reinterpret_cast<uint32_t*>(&h);
}

// ---- prep B: g_Bh = rn_f16(W) ----
__global__ void __launch_bounds__(256) prep_b(const float* __restrict__ w){
  int i = blockIdx.x * 256 + threadIdx.x;
  g_Bh[i] = __float2half_rn(w[i]);
}

// ---- prep A: pixels -> patch-major fp16 (2x-1), g_Ah[m][f], f = c*256+r*16+wc ----
__global__ void __launch_bounds__(256) prep_a(const float* __restrict__ pix){
  const int bx = blockIdx.x;          // 512 blocks: (b, ph)
  const int b  = bx >> 5, ph = bx & 31;
  const int warp = threadIdx.x >> 5, lane = threadIdx.x & 31;
  #pragma unroll 1
  for (int it = warp; it < 48; it += 8) {       // (c, r) rows
    const int c = it >> 4, r = it & 15;
    const float* src = pix + b*786432 + c*262144 + (ph*16 + r)*512;
    const int fbase = c*256 + r*16;
    #pragma unroll
    for (int p = 0; p < 4; p++) {
      const int w0 = p*128 + lane*4;
      float4 v = *reinterpret_cast<const float4*>(src + w0);
      const int pw = w0 >> 4, wc = w0 & 15;
      const int m = b*1024 + ph*32 + pw;
      uint2 u;
      u.x = pack2(fmaf(2.f, v.x, -1.f), fmaf(2.f, v.y, -1.f));
      u.y = pack2(fmaf(2.f, v.z, -1.f), fmaf(2.f, v.w, -1.f));
      *reinterpret_cast<uint2*>(&g_Ah[(size_t)m*D_DIM + fbase + wc]) = u;
    }
  }
}

// ---- main GEMM + pos-embed: pure cp.async producers, ldmatrix+mma consumers ----
__global__ void __launch_bounds__(256, 2)
gemma4_patch_embed(const float* __restrict__ ptab,     // (2,10240,768)
                   const int*   __restrict__ pids,     // (16,1024,2)
                   const int*   __restrict__ padp,     // (16,1024) bool-as-i32
                   float* __restrict__ out)            // (16,1024,768)
{
  extern __shared__ char smem[];
  const uint32_t sA = smem_u32(smem);             // 3 x ASTG
  const uint32_t sB = sA + 3*ASTG;                // 3 x BSTG
  const int t  = threadIdx.x;
  const int m0 = blockIdx.y * TBM;
  const int n0 = blockIdx.x * TBN;

  // ---- producers: thread t owns row (t>>1) and 4 16B units (half of the row) ----
  const int rr  = t >> 1;                 // 0..127
  const int ub  = (t & 1) * 4;            // unit base 0 or 4
  const __half* aSrc0 = g_Ah + (size_t)(m0 + rr)*D_DIM + ub*8;
  const __half* bSrc0 = g_Bh + (n0 + rr)*D_DIM + ub*8;
  uint32_t dstOff[4];
  #pragma unroll
  for (int u = 0; u < 4; u++)
    dstOff[u] = rr*128 + (((ub + u) ^ (rr & 7)) << 4);

  auto issueStage = [&](int s){
    const uint32_t aB = sA + (s % 3) * ASTG;
    const uint32_t bB = sB + (s % 3) * BSTG;
    const __half* as = aSrc0 + s*64;
    const __half* bs = bSrc0 + s*64;
    #pragma unroll
    for (int u = 0; u < 4; u++) {
      cpasync16(aB + dstOff[u], as + u*8);
      cpasync16(bB + dstOff[u], bs + u*8);
    }
  };

  // ---- consumer setup ----
  const int warp = t >> 5, lid = t & 31;
  const int wm = (warp >> 2) * 64;
  const int wn = (warp & 3) * 32;
  const int h16 = lid >> 4;
  const int x7  = lid & 7;
  uint32_t aLM[4], bLM[2];
  #pragma unroll
  for (int tr = 0; tr < 4; tr++)
    aLM[tr] = sA + (wm + tr*16 + (lid & 15))*128;
  #pragma unroll
  for (int ng = 0; ng < 2; ng++)
    bLM[ng] = sB + (wn + ng*16 + (lid & 15))*128;

  float acc[4][4][4];
  #pragma unroll
  for (int i = 0; i < 4; i++)
    #pragma unroll
    for (int j = 0; j < 4; j++)
      #pragma unroll
      for (int k = 0; k < 4; k++) acc[i][j][k] = 0.f;

  issueStage(0); asm volatile("cp.async.commit_group;" ::: "memory");
  issueStage(1); asm volatile("cp.async.commit_group;" ::: "memory");

  for (int s = 0; s < NSTG; s++) {
    asm volatile("cp.async.wait_group 1;" ::: "memory");
    __syncthreads();
    if (s + 2 < NSTG) issueStage(s + 2);
    asm volatile("cp.async.commit_group;" ::: "memory");

    const uint32_t aBuf = (s % 3) * ASTG;
    const uint32_t bBuf = (s % 3) * BSTG;
    #pragma unroll
    for (int kk = 0; kk < 4; kk++) {
      const uint32_t cu16 = (uint32_t)(((kk*2 + h16) ^ x7) << 4);
      uint32_t af[4][4], br[2][4];
      #pragma unroll
      for (int tr = 0; tr < 4; tr++) ldsm4(af[tr], aLM[tr] + aBuf + cu16);
      #pragma unroll
      for (int ng = 0; ng < 2; ng++) ldsm4(br[ng], bLM[ng] + bBuf + cu16);
      #pragma unroll
      for (int tm = 0; tm < 4; tm++) {
        mma16(acc[tm][0], af[tm], br[0][0], br[0][2]);
        mma16(acc[tm][1], af[tm], br[0][1], br[0][3]);
        mma16(acc[tm][2], af[tm], br[1][0], br[1][2]);
        mma16(acc[tm][3], af[tm], br[1][1], br[1][3]);
      }
    }
  }

  // ---- epilogue: add gathered position embeddings, masked by padding ----
  const int g  = lid >> 2, t4 = lid & 3;
  #pragma unroll
  for (int tm = 0; tm < 4; tm++) {
    #pragma unroll
    for (int half = 0; half < 2; half++) {
      const int lrow = wm + tm*16 + g + half*8;
      const int m = m0 + lrow;
      int x = pids[2*m];     if (x < 0) x = 0;
      int y = pids[2*m + 1]; if (y < 0) y = 0;
      const float pm = (padp[m] != 0) ? 0.f : 1.f;
      const float* p0 = ptab + x*D_DIM;
      const float* p1 = ptab + V_OFF + y*D_DIM;
      float* orow = out + (size_t)m * D_DIM + n0;
      #pragma unroll
      for (int tn = 0; tn < 4; tn++) {
        const int col = wn + tn*8 + t4*2;
        const int gc  = n0 + col;
        float2 e0 = *reinterpret_cast<const float2*>(p0 + gc);
        float2 e1 = *reinterpret_cast<const float2*>(p1 + gc);
        float2 r;
        r.x = acc[tm][tn][half*2 + 0] + pm * (e0.x + e1.x);
        r.y = acc[tm][tn][half*2 + 1] + pm * (e0.y + e1.y);
        *reinterpret_cast<float2*>(orow + col) = r;
      }
    }
  }
}

extern "C" void kernel_launch(void* const* d_in, const int* in_sizes, int n_in,
                              void* d_out, int out_size) {
  const float* pix  = (const float*)d_in[0];
  const float* w    = (const float*)d_in[1];
  const float* tab  = (const float*)d_in[2];
  const int*   pids = (const int*)d_in[3];
  const int*   padp = (const int*)d_in[4];
  float* out = (float*)d_out;

  prep_b<<<(D_DIM*D_DIM)/256, 256>>>(w);
  prep_a<<<512, 256>>>(pix);

  static int smemSet = 0;
  if (!smemSet) {
    cudaFuncSetAttribute(gemma4_patch_embed,
                         cudaFuncAttributeMaxDynamicSharedMemorySize, SMEM_TOTAL);
    smemSet = 1;
  }
  dim3 grid(D_DIM / TBN, (16 * 1024) / TBM);   // (6, 128)
  gemma4_patch_embed<<<grid, 256, SMEM_TOTAL>>>(tab, pids, padp, out);
}

// round 8
// speedup vs baseline: 1.1503x; 1.1503x over previous
#include <cuda_runtime.h>
#include <cuda_fp16.h>
#include <cstdint>

#define D_DIM 768
#define V_OFF (10240*768)
#define TBM 128
#define TBN 64
#define NSTG 12                  // K stages of 64 halfs
#define ASTG 16384               // 128 rows * 128B
#define BSTG 8192                // 64 rows * 128B
#define SMEM_TOTAL (3*(ASTG+BSTG))    // 73728

__device__ __half g_Bh[D_DIM*D_DIM];     // rn_f16(W), row-major (d, f)
__device__ __half g_Ah[16384*D_DIM];     // rn_f16(2*patch-1), (m, f)

__device__ __forceinline__ uint32_t smem_u32(const void* p){
  uint32_t a;
  asm("{ .reg .u64 t; cvta.to.shared.u64 t, %1; cvt.u32.u64 %0, t; }" : "=r"(a) : "l"(p));
  return a;
}
__device__ __forceinline__ void mma16(float* c, const uint32_t* a, uint32_t b0, uint32_t b1){
  asm volatile(
    "mma.sync.aligned.m16n8k16.row.col.f32.f16.f16.f32 "
    "{%0,%1,%2,%3},{%4,%5,%6,%7},{%8,%9},{%0,%1,%2,%3};\n"
    : "+f"(c[0]), "+f"(c[1]), "+f"(c[2]), "+f"(c[3])
    : "r"(a[0]), "r"(a[1]), "r"(a[2]), "r"(a[3]), "r"(b0), "r"(b1));
}
__device__ __forceinline__ void ldsm4(uint32_t* r, uint32_t addr){
  asm volatile("ldmatrix.sync.aligned.m8n8.x4.shared.b16 {%0,%1,%2,%3}, [%4];"
    : "=r"(r[0]), "=r"(r[1]), "=r"(r[2]), "=r"(r[3]) : "r"(addr));
}
__device__ __forceinline__ void cpasync16(uint32_t dst, const void* src){
  asm volatile("cp.async.cg.shared.global [%0], [%1], 16;"
               :: "r"(dst), "l"(src) : "memory");
}
__device__ __forceinline__ uint32_t pack2(float x, float y){
  __half2 h = __floats2half2_rn(x, y);
  return *reinterpret_cast<uint32_t*>(&h);
}

// ---- prep: g_Bh = rn_f16(W); g_Ah = rn_f16(2*patch-1) patch-major ----
__global__ void __launch_bounds__(256) prep_ab(const float* __restrict__ pix,
                                               const float* __restrict__ w){
  const int bx = blockIdx.x;          // 512 blocks: (b, ph)
  const int t  = threadIdx.x;

  // B chunk: 1152 elements per block
  #pragma unroll 1
  for (int i = t; i < 1152; i += 256) {
    int idx = bx*1152 + i;
    g_Bh[idx] = __float2half_rn(w[idx]);
  }

  // A chunk: one (b, ph) strip
  const int b  = bx >> 5, ph = bx & 31;
  const int warp = t >> 5, lane = t & 31;
  #pragma unroll 1
  for (int it = warp; it < 48; it += 8) {       // (c, r) rows
    const int c = it >> 4, r = it & 15;
    const float* src = pix + b*786432 + c*262144 + (ph*16 + r)*512;
    const int fbase = c*256 + r*16;
    #pragma unroll
    for (int p = 0; p < 4; p++) {
      const int w0 = p*128 + lane*4;
      float4 v = *reinterpret_cast<const float4*>(src + w0);
      const int pw = w0 >> 4, wc = w0 & 15;
      const int m = b*1024 + ph*32 + pw;
      uint2 u;
      u.x = pack2(fmaf(2.f, v.x, -1.f), fmaf(2.f, v.y, -1.f));
      u.y = pack2(fmaf(2.f, v.z, -1.f), fmaf(2.f, v.w, -1.f));
      *reinterpret_cast<uint2*>(&g_Ah[(size_t)m*D_DIM + fbase + wc]) = u;
    }
  }
}

// ---- main GEMM + pos-embed: 128x64 tile, 3 CTAs/SM ----
__global__ void __launch_bounds__(256, 3)
gemma4_patch_embed(const float* __restrict__ ptab,     // (2,10240,768)
                   const int*   __restrict__ pids,     // (16,1024,2)
                   const int*   __restrict__ padp,     // (16,1024) bool-as-i32
                   float* __restrict__ out)            // (16,1024,768)
{
  extern __shared__ char smem[];
  const uint32_t sA = smem_u32(smem);             // 3 x ASTG
  const uint32_t sB = sA + 3*ASTG;                // 3 x BSTG
  const int t  = threadIdx.x;
  const int m0 = blockIdx.y * TBM;
  const int n0 = blockIdx.x * TBN;

  // ---- producers ----
  // A: thread owns row (t>>1), 4 units (half row)
  const int rA  = t >> 1;
  const int ubA = (t & 1) * 4;
  const __half* aSrc0 = g_Ah + (size_t)(m0 + rA)*D_DIM + ubA*8;
  uint32_t aDst[4];
  #pragma unroll
  for (int u = 0; u < 4; u++)
    aDst[u] = rA*128 + (((ubA + u) ^ (rA & 7)) << 4);
  // B: thread owns row (t>>2), 2 units
  const int rB  = t >> 2;
  const int ubB = (t & 3) * 2;
  const __half* bSrc0 = g_Bh + (n0 + rB)*D_DIM + ubB*8;
  uint32_t bDst[2];
  #pragma unroll
  for (int u = 0; u < 2; u++)
    bDst[u] = rB*128 + (((ubB + u) ^ (rB & 7)) << 4);

  auto issueStage = [&](int s){
    const uint32_t aB = sA + (s % 3) * ASTG;
    const uint32_t bB = sB + (s % 3) * BSTG;
    const __half* as = aSrc0 + s*64;
    const __half* bs = bSrc0 + s*64;
    #pragma unroll
    for (int u = 0; u < 4; u++)
      cpasync16(aB + aDst[u], as + u*8);
    #pragma unroll
    for (int u = 0; u < 2; u++)
      cpasync16(bB + bDst[u], bs + u*8);
  };

  // ---- consumer setup: warp grid 4 (m) x 2 (n); warp tile 32x32 ----
  const int warp = t >> 5, lid = t & 31;
  const int wm = (warp >> 1) * 32;
  const int wn = (warp & 1) * 32;
  const int h16 = lid >> 4;
  const int x7  = lid & 7;
  uint32_t aLM[2], bLM[2];
  #pragma unroll
  for (int tr = 0; tr < 2; tr++)
    aLM[tr] = sA + (wm + tr*16 + (lid & 15))*128;
  #pragma unroll
  for (int ng = 0; ng < 2; ng++)
    bLM[ng] = sB + (wn + ng*16 + (lid & 15))*128;

  float acc[2][4][4];
  #pragma unroll
  for (int i = 0; i < 2; i++)
    #pragma unroll
    for (int j = 0; j < 4; j++)
      #pragma unroll
      for (int k = 0; k < 4; k++) acc[i][j][k] = 0.f;

  issueStage(0); asm volatile("cp.async.commit_group;" ::: "memory");
  issueStage(1); asm volatile("cp.async.commit_group;" ::: "memory");

  for (int s = 0; s < NSTG; s++) {
    asm volatile("cp.async.wait_group 1;" ::: "memory");
    __syncthreads();
    if (s + 2 < NSTG) issueStage(s + 2);
    asm volatile("cp.async.commit_group;" ::: "memory");

    const uint32_t aBuf = (s % 3) * ASTG;
    const uint32_t bBuf = (s % 3) * BSTG;
    #pragma unroll
    for (int kk = 0; kk < 4; kk++) {
      const uint32_t cu16 = (uint32_t)(((kk*2 + h16) ^ x7) << 4);
      uint32_t af[2][4], br[2][4];
      #pragma unroll
      for (int tr = 0; tr < 2; tr++) ldsm4(af[tr], aLM[tr] + aBuf + cu16);
      #pragma unroll
      for (int ng = 0; ng < 2; ng++) ldsm4(br[ng], bLM[ng] + bBuf + cu16);
      #pragma unroll
      for (int tm = 0; tm < 2; tm++) {
        mma16(acc[tm][0], af[tm], br[0][0], br[0][2]);
        mma16(acc[tm][1], af[tm], br[0][1], br[0][3]);
        mma16(acc[tm][2], af[tm], br[1][0], br[1][2]);
        mma16(acc[tm][3], af[tm], br[1][1], br[1][3]);
      }
    }
  }

  // ---- epilogue: add gathered position embeddings, masked by padding ----
  const int g  = lid >> 2, t4 = lid & 3;
  #pragma unroll
  for (int tm = 0; tm < 2; tm++) {
    #pragma unroll
    for (int half = 0; half < 2; half++) {
      const int lrow = wm + tm*16 + g + half*8;
      const int m = m0 + lrow;
      int x = pids[2*m];     if (x < 0) x = 0;
      int y = pids[2*m + 1]; if (y < 0) y = 0;
      const float pm = (padp[m] != 0) ? 0.f : 1.f;
      const float* p0 = ptab + x*D_DIM;
      const float* p1 = ptab + V_OFF + y*D_DIM;
      float* orow = out + (size_t)m * D_DIM + n0;
      #pragma unroll
      for (int tn = 0; tn < 4; tn++) {
        const int col = wn + tn*8 + t4*2;
        const int gc  = n0 + col;
        float2 e0 = *reinterpret_cast<const float2*>(p0 + gc);
        float2 e1 = *reinterpret_cast<const float2*>(p1 + gc);
        float2 r;
        r.x = acc[tm][tn][half*2 + 0] + pm * (e0.x + e1.x);
        r.y = acc[tm][tn][half*2 + 1] + pm * (e0.y + e1.y);
        *reinterpret_cast<float2*>(orow + col) = r;
      }
    }
  }
}

extern "C" void kernel_launch(void* const* d_in, const int* in_sizes, int n_in,
                              void* d_out, int out_size) {
  const float* pix  = (const float*)d_in[0];
  const float* w    = (const float*)d_in[1];
  const float* tab  = (const float*)d_in[2];
  const int*   pids = (const int*)d_in[3];
  const int*   padp = (const int*)d_in[4];
  float* out = (float*)d_out;

  prep_ab<<<512, 256>>>(pix, w);

  static int smemSet = 0;
  if (!smemSet) {
    cudaFuncSetAttribute(gemma4_patch_embed,
                         cudaFuncAttributeMaxDynamicSharedMemorySize, SMEM_TOTAL);
    smemSet = 1;
  }
  dim3 grid(D_DIM / TBN, (16 * 1024) / TBM);   // (12, 128)
  gemma4_patch_embed<<<grid, 256, SMEM_TOTAL>>>(tab, pids, padp, out);
}